// round 16
// baseline (speedup 1.0000x reference)
#include <cuda_runtime.h>

typedef unsigned long long ull;

#define N_NODES 100000
#define N_EDGES 1600000
#define HID 64
#define EDIM 16

// static device scratch (allocation-free)
__device__ float g_agg[(size_t)N_NODES * HID];
// g_proj[0]: x@W1[0:64]+b1 (ps) | g_proj[1]: x@W1[64:128] (pd) | g_proj[2]: x@W3[0:64]+b3 (pn)
__device__ float g_proj[(size_t)3 * N_NODES * HID];

// ---------- packed f32x2 helpers ----------
__device__ __forceinline__ ull pack2(float v) {
    ull r; asm("mov.b64 %0, {%1, %1};" : "=l"(r) : "f"(v)); return r;
}
__device__ __forceinline__ void unpack2(ull v, float& lo, float& hi) {
    asm("mov.b64 {%0, %1}, %2;" : "=f"(lo), "=f"(hi) : "l"(v));
}
__device__ __forceinline__ void ffma2(ull& d, ull a, ull b) {
    asm("fma.rn.f32x2 %0, %1, %2, %0;" : "+l"(d) : "l"(a), "l"(b));
}
__device__ __forceinline__ void fadd2(ull& d, ull a) {
    asm("add.rn.f32x2 %0, %0, %1;" : "+l"(d) : "l"(a));
}
__device__ __forceinline__ float silu_f(float v) {
    return __fdividef(v, 1.0f + __expf(-v));
}
// fast silu: v*sigmoid(v) = h + h*tanh(h), h = v/2  (1 MUFU)
__device__ __forceinline__ float silu_fast(float v) {
    float h = 0.5f * v;
    float t;
    asm("tanh.approx.f32 %0, %1;" : "=f"(t) : "f"(h));
    return fmaf(h, t, h);
}
__device__ __forceinline__ void red_add4(float* p, float a, float b, float c, float d) {
    asm volatile("red.global.add.v4.f32 [%0], {%1, %2, %3, %4};"
                 :: "l"(p), "f"(a), "f"(b), "f"(c), "f"(d) : "memory");
}

// one input value vs 64-wide weight row (32 packed FMAs, broadcast LDS)
__device__ __forceinline__ void accum1(ull* acc, ull m, const float* row) {
    const ulonglong2* r = (const ulonglong2*)row;
    #pragma unroll
    for (int j = 0; j < 16; j++) {
        ulonglong2 w = r[j];
        ffma2(acc[2 * j],     m, w.x);
        ffma2(acc[2 * j + 1], m, w.y);
    }
}
__device__ __forceinline__ void accum4(ull* acc, float4 v, const float* base) {
    accum1(acc, pack2(v.x), base);
    accum1(acc, pack2(v.y), base + HID);
    accum1(acc, pack2(v.z), base + 2 * HID);
    accum1(acc, pack2(v.w), base + 3 * HID);
}

// ---------- 1) per-node projections (+ zero agg rows) ----------
#define PROJ_SMEM ((3 * HID * HID + 3 * HID) * 4)   // 49.9 KB

__global__ void __launch_bounds__(128, 2) proj_kernel(
    const float* __restrict__ x,
    const float* __restrict__ W1, const float* __restrict__ b1,
    const float* __restrict__ W3, const float* __restrict__ b3)
{
    extern __shared__ float sm[];
    float* sW = sm;                     // [0]:W1 rows0-63  [1]:W1 rows64-127  [2]:W3 rows0-63
    float* sB = sm + 3 * HID * HID;     // [0]:b1  [1]:0  [2]:b3

    for (int i = threadIdx.x; i < 2 * HID * HID / 4; i += blockDim.x)
        ((float4*)sW)[i] = __ldg(((const float4*)W1) + i);
    for (int i = threadIdx.x; i < HID * HID / 4; i += blockDim.x)
        ((float4*)(sW + 2 * HID * HID))[i] = __ldg(((const float4*)W3) + i);
    if (threadIdx.x < HID) {
        sB[threadIdx.x]           = b1[threadIdx.x];
        sB[HID + threadIdx.x]     = 0.0f;
        sB[2 * HID + threadIdx.x] = b3[threadIdx.x];
    }
    __syncthreads();

    int n = blockIdx.x * blockDim.x + threadIdx.x;
    if (n >= N_NODES) return;

    const float4* xr = (const float4*)(x + (size_t)n * HID);
    float4 xv[16];
    #pragma unroll
    for (int k = 0; k < 16; k++) xv[k] = __ldg(xr + k);

    #pragma unroll 1
    for (int i = 0; i < 3; i++) {
        const float* w  = sW + i * HID * HID;
        const ull*   bb = (const ull*)(sB + i * HID);

        ull acc[HID / 2];
        #pragma unroll
        for (int j = 0; j < HID / 2; j++) acc[j] = bb[j];
        #pragma unroll
        for (int k4 = 0; k4 < 16; k4++)
            accum4(acc, xv[k4], w + (4 * k4) * HID);

        ull* o = (ull*)(g_proj + ((size_t)i * N_NODES + n) * HID);
        #pragma unroll
        for (int j = 0; j < HID / 2; j++) o[j] = acc[j];
    }

    // zero this node's agg row for the edge pass
    float4* az = (float4*)(g_agg + (size_t)n * HID);
    #pragma unroll
    for (int j = 0; j < 16; j++) az[j] = make_float4(0.f, 0.f, 0.f, 0.f);
}

// ---------- 2) edge MLP + scatter (chunk-parallel cooperative) ----------
// smem floats: W1e 16*64 + W2 64*64 + b2 64 + sEA 4*32*16 + sH 4*32*36
#define EDGE_SMEM ((EDIM * HID + HID * HID + HID + 4 * 32 * EDIM + 4 * 32 * 36) * 4) // 47360 B

__global__ void __launch_bounds__(128, 4) edge_kernel(
    const int* __restrict__ ei, const float* __restrict__ ea,
    const float* __restrict__ W1, const float* __restrict__ b2,
    const float* __restrict__ W2, int batch0, int nbatch)
{
    extern __shared__ float sm[];
    float* sWe    = sm;                          // [16][64]
    float* sW2    = sm + EDIM * HID;             // [64][64]
    float* sB2    = sW2 + HID * HID;             // [64]
    float* sEAall = sB2 + HID;                   // [4][32][16]
    float* sHall  = sEAall + 4 * 32 * EDIM;      // [4][32][36]

    const float* W1e = W1 + 128 * HID;
    for (int i = threadIdx.x; i < EDIM * HID / 4; i += blockDim.x)
        ((float4*)sWe)[i] = __ldg(((const float4*)W1e) + i);
    for (int i = threadIdx.x; i < HID * HID / 4; i += blockDim.x)
        ((float4*)sW2)[i] = __ldg(((const float4*)W2) + i);
    if (threadIdx.x < HID) sB2[threadIdx.x] = b2[threadIdx.x];
    __syncthreads();

    const int wid  = threadIdx.x >> 5;
    const int lane = threadIdx.x & 31;
    float* sEA = sEAall + wid * 32 * EDIM;
    float* sH  = sHall  + wid * 32 * 36;

    const int* srcp = ei;
    const int* dstp = ei + N_EDGES;
    const float* gps = g_proj;
    const float* gpd = g_proj + (size_t)N_NODES * HID;
    const float4* eaf4 = (const float4*)ea;

    const int gw = blockIdx.x * 4 + wid;   // global warp id
    const int nw = gridDim.x * 4;
    const int g_ = lane & 7;               // edge-group (4 edges each)
    const int o_ = lane >> 3;              // out-group (16 outs each)

    for (int b = batch0 + gw; b < batch0 + nbatch; b += nw) {
        const int eb = b * 32;
        const int e  = eb + lane;
        const int s  = srcp[e];
        const int d  = dstp[e];

        // stage this warp's 32 edge_attr rows (contiguous, coalesced)
        #pragma unroll
        for (int t = 0; t < 4; t++) {
            int idx4 = t * 32 + lane;
            float4 v = __ldg(eaf4 + (size_t)eb * 4 + idx4);
            *(float4*)(sEA + idx4 * 4) = v;
        }
        __syncwarp();

        // layer-2 accumulators: 4 edges x 8 f32x2 pairs, init with b2
        ull acc2[32];
        #pragma unroll
        for (int m = 0; m < 4; m++)
            #pragma unroll
            for (int j = 0; j < 8; j++)
                acc2[m * 8 + j] = ((const ull*)sB2)[o_ * 8 + j];

        #pragma unroll 1
        for (int half = 0; half < 2; half++) {
            // ---- phase A: h chunks (4 edges x 8 chunks per iteration) ----
            #pragma unroll 1
            for (int it = 0; it < 8; it++) {
                int e_loc = it * 4 + (lane >> 3);      // same within 8-lane group
                int cc    = (lane & 7) + half * 8;     // chunk index 0..15
                int ss = __shfl_sync(0xffffffffu, s, e_loc);
                int dd = __shfl_sync(0xffffffffu, d, e_loc);

                // coalesced 16B gathers: consecutive lanes -> consecutive chunks
                ulonglong2 p = *(const ulonglong2*)(gps + (size_t)ss * HID + cc * 4);
                ulonglong2 q = *(const ulonglong2*)(gpd + (size_t)dd * HID + cc * 4);
                fadd2(p.x, q.x);
                fadd2(p.y, q.y);

                #pragma unroll
                for (int k = 0; k < EDIM; k++) {
                    ull am = pack2(sEA[e_loc * EDIM + k]);          // broadcast
                    ulonglong2 w = *(const ulonglong2*)(sWe + k * HID + cc * 4);
                    ffma2(p.x, am, w.x);
                    ffma2(p.y, am, w.y);
                }
                float a0, a1, a2, a3;
                unpack2(p.x, a0, a1);
                unpack2(p.y, a2, a3);
                *(float4*)(sH + e_loc * 36 + (cc & 7) * 4) =
                    make_float4(silu_fast(a0), silu_fast(a1),
                                silu_fast(a2), silu_fast(a3));
            }
            __syncwarp();

            // ---- phase B: tiled GEMM, k = half*32 .. half*32+31 ----
            #pragma unroll 4
            for (int kk = 0; kk < 32; kk++) {
                int k = half * 32 + kk;
                float h0 = sH[(4 * g_ + 0) * 36 + kk];
                float h1 = sH[(4 * g_ + 1) * 36 + kk];
                float h2 = sH[(4 * g_ + 2) * 36 + kk];
                float h3 = sH[(4 * g_ + 3) * 36 + kk];
                ull m0 = pack2(h0), m1 = pack2(h1), m2 = pack2(h2), m3 = pack2(h3);
                const ulonglong2* wr = (const ulonglong2*)(sW2 + k * HID + o_ * 16);
                ulonglong2 w0 = wr[0], w1 = wr[1], w2v = wr[2], w3v = wr[3];

                ffma2(acc2[0],  m0, w0.x); ffma2(acc2[1],  m0, w0.y);
                ffma2(acc2[2],  m0, w1.x); ffma2(acc2[3],  m0, w1.y);
                ffma2(acc2[4],  m0, w2v.x); ffma2(acc2[5],  m0, w2v.y);
                ffma2(acc2[6],  m0, w3v.x); ffma2(acc2[7],  m0, w3v.y);

                ffma2(acc2[8],  m1, w0.x); ffma2(acc2[9],  m1, w0.y);
                ffma2(acc2[10], m1, w1.x); ffma2(acc2[11], m1, w1.y);
                ffma2(acc2[12], m1, w2v.x); ffma2(acc2[13], m1, w2v.y);
                ffma2(acc2[14], m1, w3v.x); ffma2(acc2[15], m1, w3v.y);

                ffma2(acc2[16], m2, w0.x); ffma2(acc2[17], m2, w0.y);
                ffma2(acc2[18], m2, w1.x); ffma2(acc2[19], m2, w1.y);
                ffma2(acc2[20], m2, w2v.x); ffma2(acc2[21], m2, w2v.y);
                ffma2(acc2[22], m2, w3v.x); ffma2(acc2[23], m2, w3v.y);

                ffma2(acc2[24], m3, w0.x); ffma2(acc2[25], m3, w0.y);
                ffma2(acc2[26], m3, w1.x); ffma2(acc2[27], m3, w1.y);
                ffma2(acc2[28], m3, w2v.x); ffma2(acc2[29], m3, w2v.y);
                ffma2(acc2[30], m3, w3v.x); ffma2(acc2[31], m3, w3v.y);
            }
            __syncwarp();   // sH reused by next half's phase A
        }

        // ---- epilogue: silu + scatter (4 edges x 16 outs per lane) ----
        #pragma unroll
        for (int m = 0; m < 4; m++) {
            int dd = __shfl_sync(0xffffffffu, d, 4 * g_ + m);
            float* ap = g_agg + (size_t)dd * HID + o_ * 16;
            #pragma unroll
            for (int j2 = 0; j2 < 4; j2++) {
                float a0, a1, a2, a3;
                unpack2(acc2[m * 8 + 2 * j2],     a0, a1);
                unpack2(acc2[m * 8 + 2 * j2 + 1], a2, a3);
                red_add4(ap + 4 * j2, silu_fast(a0), silu_fast(a1),
                                      silu_fast(a2), silu_fast(a3));
            }
        }
    }
}

// ---------- 3) node MLP: out = silu(pn + agg @ W3a) ----------
#define NODE_SMEM (HID * HID * 4)   // 16 KB

__global__ void __launch_bounds__(128) node_kernel(
    const float* __restrict__ W3, float* __restrict__ out)
{
    extern __shared__ float sm[];
    float* sW3a = sm;   // W3 rows 64..127

    const float* W3a = W3 + HID * HID;
    for (int i = threadIdx.x; i < HID * HID / 4; i += blockDim.x)
        ((float4*)sW3a)[i] = __ldg(((const float4*)W3a) + i);
    __syncthreads();

    int n = blockIdx.x * blockDim.x + threadIdx.x;
    if (n >= N_NODES) return;

    const float4*     ar = (const float4*)(g_agg + (size_t)n * HID);
    const ulonglong2* pr = (const ulonglong2*)(g_proj + ((size_t)2 * N_NODES + n) * HID);

    float4 av[16];
    #pragma unroll
    for (int k = 0; k < 16; k++) av[k] = __ldg(ar + k);

    ull acc[HID / 2];
    #pragma unroll
    for (int j = 0; j < 16; j++) {
        ulonglong2 p = __ldg(pr + j);
        acc[2 * j]     = p.x;
        acc[2 * j + 1] = p.y;
    }

    #pragma unroll
    for (int k4 = 0; k4 < 16; k4++)
        accum4(acc, av[k4], sW3a + (4 * k4) * HID);

    float4* op = (float4*)(out + (size_t)n * HID);
    #pragma unroll
    for (int j = 0; j < 16; j++) {
        float a0, a1, a2, a3;
        unpack2(acc[2 * j],     a0, a1);
        unpack2(acc[2 * j + 1], a2, a3);
        op[j] = make_float4(silu_f(a0), silu_f(a1), silu_f(a2), silu_f(a3));
    }
}

extern "C" void kernel_launch(void* const* d_in, const int* in_sizes, int n_in,
                              void* d_out, int out_size) {
    const float* x   = (const float*)d_in[0];
    const int*   ei  = (const int*)  d_in[1];
    const float* ea  = (const float*)d_in[2];
    const float* W1  = (const float*)d_in[3];
    const float* b1  = (const float*)d_in[4];
    const float* W2  = (const float*)d_in[5];
    const float* b2  = (const float*)d_in[6];
    const float* W3  = (const float*)d_in[7];
    const float* b3  = (const float*)d_in[8];
    float* out = (float*)d_out;

    cudaFuncSetAttribute(proj_kernel, cudaFuncAttributeMaxDynamicSharedMemorySize, PROJ_SMEM);

    int pgrid = (N_NODES + 127) / 128;
    proj_kernel<<<pgrid, 128, PROJ_SMEM>>>(x, W1, b1, W3, b3);

    // 50000 batches of 32 edges, in 3 chunks (edge chunk sits at launch pos 4)
    edge_kernel<<<592, 128, EDGE_SMEM>>>(ei, ea, W1, b2, W2,     0, 16667);
    edge_kernel<<<592, 128, EDGE_SMEM>>>(ei, ea, W1, b2, W2, 16667, 16667);
    edge_kernel<<<592, 128, EDGE_SMEM>>>(ei, ea, W1, b2, W2, 33334, 16666);

    node_kernel<<<pgrid, 128, NODE_SMEM>>>(W3, out);
}

// round 17
// speedup vs baseline: 1.0011x; 1.0011x over previous
#include <cuda_runtime.h>

typedef unsigned long long ull;

#define N_NODES 100000
#define N_EDGES 1600000
#define HID 64
#define EDIM 16

// static device scratch (allocation-free)
__device__ float g_agg[(size_t)N_NODES * HID];
// g_proj[0]: x@W1[0:64]+b1 (ps) | g_proj[1]: x@W1[64:128] (pd) | g_proj[2]: x@W3[0:64]+b3 (pn)
__device__ float g_proj[(size_t)3 * N_NODES * HID];

// ---------- packed f32x2 helpers ----------
__device__ __forceinline__ ull pack2(float v) {
    ull r; asm("mov.b64 %0, {%1, %1};" : "=l"(r) : "f"(v)); return r;
}
__device__ __forceinline__ void unpack2(ull v, float& lo, float& hi) {
    asm("mov.b64 {%0, %1}, %2;" : "=f"(lo), "=f"(hi) : "l"(v));
}
__device__ __forceinline__ void ffma2(ull& d, ull a, ull b) {
    asm("fma.rn.f32x2 %0, %1, %2, %0;" : "+l"(d) : "l"(a), "l"(b));
}
__device__ __forceinline__ void fadd2(ull& d, ull a) {
    asm("add.rn.f32x2 %0, %0, %1;" : "+l"(d) : "l"(a));
}
__device__ __forceinline__ float silu_f(float v) {
    return __fdividef(v, 1.0f + __expf(-v));
}
// fast silu: v*sigmoid(v) = h + h*tanh(h), h = v/2  (1 MUFU)
__device__ __forceinline__ float silu_fast(float v) {
    float h = 0.5f * v;
    float t;
    asm("tanh.approx.f32 %0, %1;" : "=f"(t) : "f"(h));
    return fmaf(h, t, h);
}
__device__ __forceinline__ void red_add4(float* p, float a, float b, float c, float d) {
    asm volatile("red.global.add.v4.f32 [%0], {%1, %2, %3, %4};"
                 :: "l"(p), "f"(a), "f"(b), "f"(c), "f"(d) : "memory");
}

// one input value vs 64-wide weight row (32 packed FMAs, broadcast LDS)
__device__ __forceinline__ void accum1(ull* acc, ull m, const float* row) {
    const ulonglong2* r = (const ulonglong2*)row;
    #pragma unroll
    for (int j = 0; j < 16; j++) {
        ulonglong2 w = r[j];
        ffma2(acc[2 * j],     m, w.x);
        ffma2(acc[2 * j + 1], m, w.y);
    }
}
__device__ __forceinline__ void accum4(ull* acc, float4 v, const float* base) {
    accum1(acc, pack2(v.x), base);
    accum1(acc, pack2(v.y), base + HID);
    accum1(acc, pack2(v.z), base + 2 * HID);
    accum1(acc, pack2(v.w), base + 3 * HID);
}

// ---------- 1) per-node projections (+ zero agg rows) ----------
#define PROJ_SMEM ((3 * HID * HID + 3 * HID) * 4)   // 49.9 KB

__global__ void __launch_bounds__(128, 2) proj_kernel(
    const float* __restrict__ x,
    const float* __restrict__ W1, const float* __restrict__ b1,
    const float* __restrict__ W3, const float* __restrict__ b3)
{
    extern __shared__ float sm[];
    float* sW = sm;                     // [0]:W1 rows0-63  [1]:W1 rows64-127  [2]:W3 rows0-63
    float* sB = sm + 3 * HID * HID;     // [0]:b1  [1]:0  [2]:b3

    for (int i = threadIdx.x; i < 2 * HID * HID / 4; i += blockDim.x)
        ((float4*)sW)[i] = __ldg(((const float4*)W1) + i);
    for (int i = threadIdx.x; i < HID * HID / 4; i += blockDim.x)
        ((float4*)(sW + 2 * HID * HID))[i] = __ldg(((const float4*)W3) + i);
    if (threadIdx.x < HID) {
        sB[threadIdx.x]           = b1[threadIdx.x];
        sB[HID + threadIdx.x]     = 0.0f;
        sB[2 * HID + threadIdx.x] = b3[threadIdx.x];
    }
    __syncthreads();

    int n = blockIdx.x * blockDim.x + threadIdx.x;
    if (n >= N_NODES) return;

    const float4* xr = (const float4*)(x + (size_t)n * HID);
    float4 xv[16];
    #pragma unroll
    for (int k = 0; k < 16; k++) xv[k] = __ldg(xr + k);

    #pragma unroll 1
    for (int i = 0; i < 3; i++) {
        const float* w  = sW + i * HID * HID;
        const ull*   bb = (const ull*)(sB + i * HID);

        ull acc[HID / 2];
        #pragma unroll
        for (int j = 0; j < HID / 2; j++) acc[j] = bb[j];
        #pragma unroll
        for (int k4 = 0; k4 < 16; k4++)
            accum4(acc, xv[k4], w + (4 * k4) * HID);

        ull* o = (ull*)(g_proj + ((size_t)i * N_NODES + n) * HID);
        #pragma unroll
        for (int j = 0; j < HID / 2; j++) o[j] = acc[j];
    }

    // zero this node's agg row for the edge pass
    float4* az = (float4*)(g_agg + (size_t)n * HID);
    #pragma unroll
    for (int j = 0; j < 16; j++) az[j] = make_float4(0.f, 0.f, 0.f, 0.f);
}

// ---------- 2) edge MLP + scatter (chunk-parallel cooperative) ----------
// smem floats: W1e 16*64 + W2 64*64 + b2 64 + sEA 4*32*16 + sH 4*32*36
#define EDGE_SMEM ((EDIM * HID + HID * HID + HID + 4 * 32 * EDIM + 4 * 32 * 36) * 4) // 47360 B

__global__ void __launch_bounds__(128, 4) edge_kernel(
    const int* __restrict__ ei, const float* __restrict__ ea,
    const float* __restrict__ W1, const float* __restrict__ b2,
    const float* __restrict__ W2, int batch0, int nbatch)
{
    extern __shared__ float sm[];
    float* sWe    = sm;                          // [16][64]
    float* sW2    = sm + EDIM * HID;             // [64][64]
    float* sB2    = sW2 + HID * HID;             // [64]
    float* sEAall = sB2 + HID;                   // [4][32][16]
    float* sHall  = sEAall + 4 * 32 * EDIM;      // [4][32][36]

    const float* W1e = W1 + 128 * HID;
    for (int i = threadIdx.x; i < EDIM * HID / 4; i += blockDim.x)
        ((float4*)sWe)[i] = __ldg(((const float4*)W1e) + i);
    for (int i = threadIdx.x; i < HID * HID / 4; i += blockDim.x)
        ((float4*)sW2)[i] = __ldg(((const float4*)W2) + i);
    if (threadIdx.x < HID) sB2[threadIdx.x] = b2[threadIdx.x];
    __syncthreads();

    const int wid  = threadIdx.x >> 5;
    const int lane = threadIdx.x & 31;
    float* sEA = sEAall + wid * 32 * EDIM;
    float* sH  = sHall  + wid * 32 * 36;

    const int* srcp = ei;
    const int* dstp = ei + N_EDGES;
    const float* gps = g_proj;
    const float* gpd = g_proj + (size_t)N_NODES * HID;
    const float4* eaf4 = (const float4*)ea;

    const int gw = blockIdx.x * 4 + wid;   // global warp id
    const int nw = gridDim.x * 4;
    const int g_ = lane & 7;               // edge-group (4 edges each)
    const int o_ = lane >> 3;              // out-group (16 outs each)

    for (int b = batch0 + gw; b < batch0 + nbatch; b += nw) {
        const int eb = b * 32;
        const int e  = eb + lane;
        const int s  = srcp[e];
        const int d  = dstp[e];

        // stage this warp's 32 edge_attr rows (contiguous, coalesced)
        #pragma unroll
        for (int t = 0; t < 4; t++) {
            int idx4 = t * 32 + lane;
            float4 v = __ldg(eaf4 + (size_t)eb * 4 + idx4);
            *(float4*)(sEA + idx4 * 4) = v;
        }
        __syncwarp();

        // layer-2 accumulators: 4 edges x 8 f32x2 pairs, init with b2
        ull acc2[32];
        #pragma unroll
        for (int m = 0; m < 4; m++)
            #pragma unroll
            for (int j = 0; j < 8; j++)
                acc2[m * 8 + j] = ((const ull*)sB2)[o_ * 8 + j];

        #pragma unroll 1
        for (int half = 0; half < 2; half++) {
            // ---- phase A: h chunks (4 edges x 8 chunks per iteration) ----
            #pragma unroll 1
            for (int it = 0; it < 8; it++) {
                int e_loc = it * 4 + (lane >> 3);      // same within 8-lane group
                int cc    = (lane & 7) + half * 8;     // chunk index 0..15
                int ss = __shfl_sync(0xffffffffu, s, e_loc);
                int dd = __shfl_sync(0xffffffffu, d, e_loc);

                // coalesced 16B gathers: consecutive lanes -> consecutive chunks
                ulonglong2 p = *(const ulonglong2*)(gps + (size_t)ss * HID + cc * 4);
                ulonglong2 q = *(const ulonglong2*)(gpd + (size_t)dd * HID + cc * 4);
                fadd2(p.x, q.x);
                fadd2(p.y, q.y);

                #pragma unroll
                for (int k = 0; k < EDIM; k++) {
                    ull am = pack2(sEA[e_loc * EDIM + k]);          // broadcast
                    ulonglong2 w = *(const ulonglong2*)(sWe + k * HID + cc * 4);
                    ffma2(p.x, am, w.x);
                    ffma2(p.y, am, w.y);
                }
                float a0, a1, a2, a3;
                unpack2(p.x, a0, a1);
                unpack2(p.y, a2, a3);
                *(float4*)(sH + e_loc * 36 + (cc & 7) * 4) =
                    make_float4(silu_fast(a0), silu_fast(a1),
                                silu_fast(a2), silu_fast(a3));
            }
            __syncwarp();

            // ---- phase B: tiled GEMM, k = half*32 .. half*32+31 ----
            #pragma unroll 4
            for (int kk = 0; kk < 32; kk++) {
                int k = half * 32 + kk;
                float h0 = sH[(4 * g_ + 0) * 36 + kk];
                float h1 = sH[(4 * g_ + 1) * 36 + kk];
                float h2 = sH[(4 * g_ + 2) * 36 + kk];
                float h3 = sH[(4 * g_ + 3) * 36 + kk];
                ull m0 = pack2(h0), m1 = pack2(h1), m2 = pack2(h2), m3 = pack2(h3);
                const ulonglong2* wr = (const ulonglong2*)(sW2 + k * HID + o_ * 16);
                ulonglong2 w0 = wr[0], w1 = wr[1], w2v = wr[2], w3v = wr[3];

                ffma2(acc2[0],  m0, w0.x); ffma2(acc2[1],  m0, w0.y);
                ffma2(acc2[2],  m0, w1.x); ffma2(acc2[3],  m0, w1.y);
                ffma2(acc2[4],  m0, w2v.x); ffma2(acc2[5],  m0, w2v.y);
                ffma2(acc2[6],  m0, w3v.x); ffma2(acc2[7],  m0, w3v.y);

                ffma2(acc2[8],  m1, w0.x); ffma2(acc2[9],  m1, w0.y);
                ffma2(acc2[10], m1, w1.x); ffma2(acc2[11], m1, w1.y);
                ffma2(acc2[12], m1, w2v.x); ffma2(acc2[13], m1, w2v.y);
                ffma2(acc2[14], m1, w3v.x); ffma2(acc2[15], m1, w3v.y);

                ffma2(acc2[16], m2, w0.x); ffma2(acc2[17], m2, w0.y);
                ffma2(acc2[18], m2, w1.x); ffma2(acc2[19], m2, w1.y);
                ffma2(acc2[20], m2, w2v.x); ffma2(acc2[21], m2, w2v.y);
                ffma2(acc2[22], m2, w3v.x); ffma2(acc2[23], m2, w3v.y);

                ffma2(acc2[24], m3, w0.x); ffma2(acc2[25], m3, w0.y);
                ffma2(acc2[26], m3, w1.x); ffma2(acc2[27], m3, w1.y);
                ffma2(acc2[28], m3, w2v.x); ffma2(acc2[29], m3, w2v.y);
                ffma2(acc2[30], m3, w3v.x); ffma2(acc2[31], m3, w3v.y);
            }
            __syncwarp();   // sH reused by next half's phase A
        }

        // ---- epilogue: silu + scatter (4 edges x 16 outs per lane) ----
        #pragma unroll
        for (int m = 0; m < 4; m++) {
            int dd = __shfl_sync(0xffffffffu, d, 4 * g_ + m);
            float* ap = g_agg + (size_t)dd * HID + o_ * 16;
            #pragma unroll
            for (int j2 = 0; j2 < 4; j2++) {
                float a0, a1, a2, a3;
                unpack2(acc2[m * 8 + 2 * j2],     a0, a1);
                unpack2(acc2[m * 8 + 2 * j2 + 1], a2, a3);
                red_add4(ap + 4 * j2, silu_fast(a0), silu_fast(a1),
                                      silu_fast(a2), silu_fast(a3));
            }
        }
    }
}

// ---------- 3) node MLP: out = silu(pn + agg @ W3a) ----------
#define NODE_SMEM (HID * HID * 4)   // 16 KB

__global__ void __launch_bounds__(128) node_kernel(
    const float* __restrict__ W3, float* __restrict__ out)
{
    extern __shared__ float sm[];
    float* sW3a = sm;   // W3 rows 64..127

    const float* W3a = W3 + HID * HID;
    for (int i = threadIdx.x; i < HID * HID / 4; i += blockDim.x)
        ((float4*)sW3a)[i] = __ldg(((const float4*)W3a) + i);
    __syncthreads();

    int n = blockIdx.x * blockDim.x + threadIdx.x;
    if (n >= N_NODES) return;

    const float4*     ar = (const float4*)(g_agg + (size_t)n * HID);
    const ulonglong2* pr = (const ulonglong2*)(g_proj + ((size_t)2 * N_NODES + n) * HID);

    float4 av[16];
    #pragma unroll
    for (int k = 0; k < 16; k++) av[k] = __ldg(ar + k);

    ull acc[HID / 2];
    #pragma unroll
    for (int j = 0; j < 16; j++) {
        ulonglong2 p = __ldg(pr + j);
        acc[2 * j]     = p.x;
        acc[2 * j + 1] = p.y;
    }

    #pragma unroll
    for (int k4 = 0; k4 < 16; k4++)
        accum4(acc, av[k4], sW3a + (4 * k4) * HID);

    float4* op = (float4*)(out + (size_t)n * HID);
    #pragma unroll
    for (int j = 0; j < 16; j++) {
        float a0, a1, a2, a3;
        unpack2(acc[2 * j],     a0, a1);
        unpack2(acc[2 * j + 1], a2, a3);
        op[j] = make_float4(silu_f(a0), silu_f(a1), silu_f(a2), silu_f(a3));
    }
}

extern "C" void kernel_launch(void* const* d_in, const int* in_sizes, int n_in,
                              void* d_out, int out_size) {
    const float* x   = (const float*)d_in[0];
    const int*   ei  = (const int*)  d_in[1];
    const float* ea  = (const float*)d_in[2];
    const float* W1  = (const float*)d_in[3];
    const float* b1  = (const float*)d_in[4];
    const float* W2  = (const float*)d_in[5];
    const float* b2  = (const float*)d_in[6];
    const float* W3  = (const float*)d_in[7];
    const float* b3  = (const float*)d_in[8];
    float* out = (float*)d_out;

    cudaFuncSetAttribute(proj_kernel, cudaFuncAttributeMaxDynamicSharedMemorySize, PROJ_SMEM);

    int pgrid = (N_NODES + 127) / 128;
    proj_kernel<<<pgrid, 128, PROJ_SMEM>>>(x, W1, b1, W3, b3);

    // 50000 batches of 32 edges, in 3 chunks (edge chunk sits at launch pos 4)
    edge_kernel<<<592, 128, EDGE_SMEM>>>(ei, ea, W1, b2, W2,     0, 16667);
    edge_kernel<<<592, 128, EDGE_SMEM>>>(ei, ea, W1, b2, W2, 16667, 16667);
    edge_kernel<<<592, 128, EDGE_SMEM>>>(ei, ea, W1, b2, W2, 33334, 16666);

    node_kernel<<<pgrid, 128, NODE_SMEM>>>(W3, out);
}